// round 11
// baseline (speedup 1.0000x reference)
#include <cuda_runtime.h>

#define BB 4
#define ROI 90
#define TT 200
#define HH 3
#define FF 96
#define G3 288
#define NB 12   // BB*HH
#define SEQ_GROUPS 3
#define SEQ_PER 4   // NB / SEQ_GROUPS

typedef unsigned long long u64;

// scratch (device globals; no runtime alloc allowed)
__device__ float g_act[(size_t)NB * ROI * TT * FF];        // (n, roi, t, f)

__device__ __forceinline__ u64 pk2(float lo, float hi) {
    u64 r; asm("mov.b64 %0,{%1,%2};" : "=l"(r) : "f"(lo), "f"(hi)); return r;
}
__device__ __forceinline__ void fma2(u64& d, u64 a, u64 b) {
    asm("fma.rn.f32x2 %0,%1,%2,%3;" : "=l"(d) : "l"(a), "l"(b), "l"(d));
}
__device__ __forceinline__ float red2(u64 v) {
    float lo, hi; asm("mov.b64 {%0,%1},%2;" : "=f"(lo), "=f"(hi) : "l"(v));
    return lo + hi;
}
__device__ __forceinline__ float sigmoidf_fast(float x) {
    return __fdividef(1.0f, 1.0f + __expf(-x));
}
__device__ __forceinline__ float tanhf_fast(float x) {
    float e = __expf(2.0f * x);
    return 1.0f - __fdividef(2.0f, e + 1.0f);
}

// ---------------------------------------------------------------------------
// K1 (R10 version, proven 372us): per-(b,t,h, row-half) block, maxreg 75.
// ---------------------------------------------------------------------------
__global__ __launch_bounds__(288, 3) void k1_agg_mlp(
    const float* __restrict__ x, const float* __restrict__ a,
    const float* __restrict__ eps,
    const float* __restrict__ W1, const float* __restrict__ b1,
    const float* __restrict__ g1, const float* __restrict__ be1,
    const float* __restrict__ W2, const float* __restrict__ b2,
    const float* __restrict__ g2, const float* __restrict__ be2)
{
    extern __shared__ float sm[];
    float* xs  = sm;              // 8640 floats
    float* buf = sm + 8640;       // 4320 floats
    unsigned char* idx8 = (unsigned char*)(sm + 8640 + 4320);  // 45*96 bytes
    int* cnts = (int*)(idx8 + 45 * 96);                        // 45 ints

    const int bid = blockIdx.x;
    const int half = blockIdx.y;
    const int b   = bid / (TT * HH);
    const int rem = bid % (TT * HH);
    const int t   = rem / HH;
    const int hh  = rem % HH;
    const int tid = threadIdx.x;

    {
        const float4* xsrc = (const float4*)x;
        for (int idx = tid; idx < ROI * 24; idx += 288) {
            int i = idx / 24, c4 = idx % 24;
            ((float4*)xs)[i * 24 + c4] =
                xsrc[(((((size_t)b * ROI + i) * TT + t) * HH + hh) * FF) / 4 + c4];
        }
    }

    const int warp = tid >> 5, lane = tid & 31;
    for (int r = warp; r < 45; r += 9) {
        int i = half * 45 + r;
        size_t aoff = ((((size_t)b * ROI + i) * TT + t) * HH + hh) * ROI;
        int cnt = 0;
        #pragma unroll
        for (int c0 = 0; c0 < 96; c0 += 32) {
            int j = c0 + lane;
            float v = (j < ROI) ? a[aoff + j] : 0.0f;
            unsigned m = __ballot_sync(0xffffffffu, v != 0.0f);
            if (v != 0.0f) {
                int pos = cnt + __popc(m & ((1u << lane) - 1u));
                idx8[r * 96 + pos] = (unsigned char)j;
            }
            cnt += __popc(m);
        }
        if (lane == 0) cnts[r] = cnt;
    }
    __syncthreads();

    const float epsv = eps[0];

    {
        const int c4 = tid % 24;
        const int ig = tid / 24;
        for (int r = ig; r < 45; r += 12) {
            int i = half * 45 + r;
            float4 base = ((const float4*)xs)[i * 24 + c4];
            float4 s = make_float4(epsv * base.x, epsv * base.y,
                                   epsv * base.z, epsv * base.w);
            int cnt = cnts[r];
            const unsigned char* il = idx8 + r * 96;
            for (int s0 = 0; s0 < cnt; s0++) {
                int j = il[s0];
                float4 v = ((const float4*)xs)[j * 24 + c4];
                s.x += v.x; s.y += v.y; s.z += v.z; s.w += v.w;
            }
            ((float4*)buf)[r * 24 + c4] = s;
        }
    }
    __syncthreads();

    const int c  = tid % 96;
    const int ib = tid / 96;

    // GEMM1
    {
        u64 acc[15];
        #pragma unroll
        for (int r = 0; r < 15; r++) acc[r] = 0ull;
        #pragma unroll 2
        for (int k = 0; k < 96; k += 4) {
            float wa = __ldg(&W1[(k + 0) * 96 + c]);
            float wb = __ldg(&W1[(k + 1) * 96 + c]);
            float wc = __ldg(&W1[(k + 2) * 96 + c]);
            float wd = __ldg(&W1[(k + 3) * 96 + c]);
            u64 w01 = pk2(wa, wb), w23 = pk2(wc, wd);
            #pragma unroll
            for (int r = 0; r < 15; r++) {
                ulonglong2 av = *(const ulonglong2*)&buf[(ib + 3 * r) * 96 + k];
                fma2(acc[r], av.x, w01);
                fma2(acc[r], av.y, w23);
            }
        }
        float gs  = g1[c] * rsqrtf(1.0f + 1e-5f);
        float bbv = be1[c];
        float b1c = b1[c];
        __syncthreads();
        #pragma unroll
        for (int r = 0; r < 15; r++) {
            int rr = ib + 3 * r;
            float y = (red2(acc[r]) + b1c) * gs + bbv;
            y = (y > 0.0f) ? y : (__expf(y) - 1.0f);
            xs[rr * 96 + c] = y;
        }
    }
    __syncthreads();

    // GEMM2
    {
        u64 acc[15];
        #pragma unroll
        for (int r = 0; r < 15; r++) acc[r] = 0ull;
        #pragma unroll 2
        for (int k = 0; k < 96; k += 4) {
            float wa = __ldg(&W2[(k + 0) * 96 + c]);
            float wb = __ldg(&W2[(k + 1) * 96 + c]);
            float wc = __ldg(&W2[(k + 2) * 96 + c]);
            float wd = __ldg(&W2[(k + 3) * 96 + c]);
            u64 w01 = pk2(wa, wb), w23 = pk2(wc, wd);
            #pragma unroll
            for (int r = 0; r < 15; r++) {
                ulonglong2 av = *(const ulonglong2*)&xs[(ib + 3 * r) * 96 + k];
                fma2(acc[r], av.x, w01);
                fma2(acc[r], av.y, w23);
            }
        }
        float gs  = g2[c] * rsqrtf(1.0f + 1e-5f);
        float bbv = be2[c];
        float b2c = b2[c];
        const int n = b * HH + hh;
        #pragma unroll
        for (int r = 0; r < 15; r++) {
            int i = half * 45 + ib + 3 * r;
            float y = (red2(acc[r]) + b2c) * gs + bbv;
            y = fmaxf(y, 0.0f);
            g_act[(((size_t)n * ROI + i) * TT + t) * FF + c] = y;
        }
    }
}

// ---------------------------------------------------------------------------
// K23: fused input-projection + GRU recurrence.
//     grid (90, 3): one block per (roi, 4-seq group); 576 threads = 288 g x 2 kh.
//     Wih[roi] in smem (u64, transposed: wih2[kk*288+g]); Whh half-row in regs.
//     Activations double-buffered with register prefetch; 3 barriers/step.
// smem (floats):
//   wih2   [0, 27648)        13824 u64
//   acts   [27648, 28416)    2 x 4 x 96
//   hbuf   [28416, 28800)    4 x 96
//   rbuf   [28800, 29184)
//   zbuf   [29184, 29568)
//   xpart  [29568, 30720)    4 x 288
//   hpart  [30720, 31872)    4 x 288
// total 127,488 B
// ---------------------------------------------------------------------------
__global__ __launch_bounds__(576, 1) void k23_fused(
    const float* __restrict__ Wih, const float* __restrict__ bih,
    const float* __restrict__ Whh, const float* __restrict__ bhh,
    float* __restrict__ out)
{
    extern __shared__ float sm[];
    u64*   wih2  = (u64*)sm;            // [48][288] u64 (kk-major, transposed)
    float* acts  = sm + 27648;          // [2][4][96]
    float* hbuf  = sm + 28416;          // [4][96]
    float* rbuf  = sm + 28800;
    float* zbuf  = sm + 29184;
    float* xpart = sm + 29568;          // [4][288]
    float* hpart = sm + 30720;          // [4][288]

    const int roi = blockIdx.x;
    const int sg  = blockIdx.y;
    const int tid = threadIdx.x;
    const int g   = tid % G3;
    const int kh  = tid / G3;           // 0: k[0,48)  1: k[48,96)

    // stage Wih[roi] transposed into smem: wih2[(2q+e)*288 + g]
    {
        const float4* wsrc4 = (const float4*)(Wih + (size_t)roi * G3 * 96);
        #pragma unroll
        for (int it = 0; it < 12; it++) {
            int idx = it * 576 + tid;          // 288*24 = 6912 float4
            int gg = idx / 24, q = idx % 24;
            float4 v = __ldg(&wsrc4[gg * 24 + q]);
            wih2[(2 * q + 0) * G3 + gg] = pk2(v.x, v.y);
            wih2[(2 * q + 1) * G3 + gg] = pk2(v.z, v.w);
        }
    }

    // Whh half-row in registers
    u64 wr2[24];
    {
        const ulonglong2* wsrc =
            (const ulonglong2*)(Whh + ((size_t)roi * G3 + g) * 96 + kh * 48);
        #pragma unroll
        for (int kk = 0; kk < 12; kk++) {
            ulonglong2 w = __ldg(&wsrc[kk]);
            wr2[2 * kk + 0] = w.x;
            wr2[2 * kk + 1] = w.y;
        }
    }
    const float bvi = __ldg(&bih[roi * G3 + g]);
    const float bvh = __ldg(&bhh[roi * G3 + g]);

    // init h = 0; stage acts for t=0
    for (int idx = tid; idx < SEQ_PER * 96; idx += 576) hbuf[idx] = 0.0f;
    const int sn = tid / 24, sc4 = tid % 24;   // staging role for tid < 96
    if (tid < 96) {
        ((float4*)acts)[tid] = __ldg(&((const float4*)g_act)
            [((((size_t)(sg * SEQ_PER + sn) * ROI + roi) * TT + 0) * FF) / 4 + sc4]);
    }
    __syncthreads();

    const int gtype = g / 96;   // 0:r  1:z  2:n
    const int j     = g % 96;
    const u64* wcol = wih2 + (size_t)(kh * 24) * G3 + g;

    for (int t = 0; t < TT; t++) {
        const int cur = t & 1, nxt = cur ^ 1;
        const float* ac = acts + cur * (SEQ_PER * 96);

        // issue prefetch of next step's activation rows
        float4 pf;
        const bool havepf = (tid < 96) && (t + 1 < TT);
        if (havepf) {
            pf = __ldg(&((const float4*)g_act)
                [((((size_t)(sg * SEQ_PER + sn) * ROI + roi) * TT + (t + 1)) * FF) / 4 + sc4]);
        }

        // xq[n] = act[n] . Wih_half[g]   (weights from smem, lane-consecutive)
        u64 xq[SEQ_PER];
        #pragma unroll
        for (int n = 0; n < SEQ_PER; n++) xq[n] = 0ull;
        #pragma unroll
        for (int kk = 0; kk < 24; kk++) {
            u64 w = wcol[(size_t)kk * G3];
            #pragma unroll
            for (int n = 0; n < SEQ_PER; n++) {
                u64 av = *(const u64*)&ac[n * 96 + kh * 48 + 2 * kk];
                fma2(xq[n], av, w);
            }
        }

        // hp[n] = h[n] . Whh_half[g]   (weights in regs)
        u64 hq[SEQ_PER];
        #pragma unroll
        for (int n = 0; n < SEQ_PER; n++) hq[n] = 0ull;
        #pragma unroll
        for (int kk = 0; kk < 12; kk++) {
            #pragma unroll
            for (int n = 0; n < SEQ_PER; n++) {
                ulonglong2 hv = *(const ulonglong2*)&hbuf[n * 96 + kh * 48 + 8 * kk / 2];
                fma2(hq[n], hv.x, wr2[2 * kk + 0]);
                fma2(hq[n], hv.y, wr2[2 * kk + 1]);
            }
        }

        if (kh == 1) {
            #pragma unroll
            for (int n = 0; n < SEQ_PER; n++) {
                xpart[n * G3 + g] = red2(xq[n]);
                hpart[n * G3 + g] = red2(hq[n]);
            }
        }
        if (havepf) ((float4*)acts)[nxt * 96 + tid] = pf;
        __syncthreads();   // barrier 1

        float xv[SEQ_PER], hp[SEQ_PER];
        if (kh == 0) {
            #pragma unroll
            for (int n = 0; n < SEQ_PER; n++) {
                xv[n] = red2(xq[n]) + xpart[n * G3 + g] + bvi;
                hp[n] = red2(hq[n]) + hpart[n * G3 + g] + bvh;
            }
            if (gtype < 2) {
                float* dst = (gtype == 0) ? rbuf : zbuf;
                #pragma unroll
                for (int n = 0; n < SEQ_PER; n++)
                    dst[n * 96 + j] = sigmoidf_fast(xv[n] + hp[n]);
            }
        }
        __syncthreads();   // barrier 2

        if (kh == 0 && gtype == 2) {
            #pragma unroll
            for (int n = 0; n < SEQ_PER; n++) {
                float r  = rbuf[n * 96 + j];
                float z  = zbuf[n * 96 + j];
                float hn = tanhf_fast(xv[n] + r * hp[n]);
                float h0 = hbuf[n * 96 + j];
                float h2 = (1.0f - z) * hn + z * h0;
                hbuf[n * 96 + j] = h2;
                int nn = sg * SEQ_PER + n;
                int b  = nn / HH, hh = nn % HH;
                out[((((size_t)b * ROI + roi) * TT + t) * HH + hh) * 96 + j] = h2;
            }
        }
        __syncthreads();   // barrier 3 (hbuf update visible to next step)
    }
}

// ---------------------------------------------------------------------------
extern "C" void kernel_launch(void* const* d_in, const int* in_sizes, int n_in,
                              void* d_out, int out_size)
{
    const float* x   = (const float*)d_in[0];
    const float* a   = (const float*)d_in[1];
    const float* eps = (const float*)d_in[2];
    const float* W1  = (const float*)d_in[3];
    const float* b1  = (const float*)d_in[4];
    const float* g1  = (const float*)d_in[5];
    const float* be1 = (const float*)d_in[6];
    const float* W2  = (const float*)d_in[7];
    const float* b2  = (const float*)d_in[8];
    const float* g2  = (const float*)d_in[9];
    const float* be2 = (const float*)d_in[10];
    const float* Wih = (const float*)d_in[11];
    const float* Whh = (const float*)d_in[12];
    const float* bih = (const float*)d_in[13];
    const float* bhh = (const float*)d_in[14];
    float* out = (float*)d_out;

    const int smem1 = (8640 + 4320) * 4 + 45 * 96 + 45 * 4;   // 56,340 B
    cudaFuncSetAttribute(k1_agg_mlp, cudaFuncAttributeMaxDynamicSharedMemorySize, smem1);

    const int smem23 = 31872 * 4;                             // 127,488 B
    cudaFuncSetAttribute(k23_fused, cudaFuncAttributeMaxDynamicSharedMemorySize, smem23);

    k1_agg_mlp<<<dim3(BB * TT * HH, 2), 288, smem1>>>(x, a, eps, W1, b1, g1, be1,
                                                      W2, b2, g2, be2);
    k23_fused<<<dim3(ROI, SEQ_GROUPS), 576, smem23>>>(Wih, bih, Whh, bhh, out);
}